// round 12
// baseline (speedup 1.0000x reference)
#include <cuda_runtime.h>

#define NUM_CODES 1024
#define TPB 128          // 4 warps
#define HPAD 5           // each hist bin on its own 128B line
#define TROWS 16         // rows per sub-tile (4KB)
#define NT 8             // sub-tiles per warp -> 128 rows/warp, 512 rows/block

__device__ int g_hist[NUM_CODES << HPAD];   // zero at load
__device__ unsigned int g_done;             // zero at load

// stage one 16-row sub-tile: 8 LDGSTS per lane, contiguous 512B per instruction
__device__ __forceinline__ void prefetch_tile(float4* dst, const float4* src) {
    const int lane = threadIdx.x & 31;
    #pragma unroll
    for (int i = 0; i < 8; i++) {
        int f = lane + i * 32;
        int r = f >> 4, c = f & 15;
        int slot = (r << 4) | (c ^ (r & 7));       // conflict-free swizzle
        unsigned int d = (unsigned int)__cvta_generic_to_shared(dst + slot);
        asm volatile("cp.async.cg.shared.global [%0], [%1], 16;\n"
                     :: "r"(d), "l"(src + f) : "memory");
    }
    asm volatile("cp.async.commit_group;\n" ::: "memory");
}

// ---------------------------------------------------------------------------
// Per-warp double-buffered pipeline: while computing sub-tile s from one 4KB
// buffer, cp.async streams sub-tile s+1 into the other. No __syncthreads in
// the hot path; 24 warps/SM each keep a load group in flight continuously.
// Lane pair (l, l+16) shares row l&15 (half a row each), combined via 4
// shfl_xor(16); both lanes quantize redundantly (no broadcast shuffles).
// ---------------------------------------------------------------------------
__global__ __launch_bounds__(TPB, 6) void fsq_main(
    const float* __restrict__ ze,    // (B, 64)
    const float* __restrict__ Win,   // (4, 64) row-major
    const float4* __restrict__ Wout4,// (64) float4 rows
    float* __restrict__ zq,          // (B, 64)
    float* __restrict__ idx_out,     // (B,)
    float* __restrict__ scal,        // 4 scalars
    float invB)
{
    __shared__ float4 buf[4][2][TROWS * 16];   // 4 warps x 2 x 4KB = 32KB
    __shared__ float  sWin[256];               // 4 x 64
    __shared__ float4 sC[4][TROWS];            // centered codes per warp-tile
    __shared__ bool   isLast;
    __shared__ float  red[8];

    const int t    = threadIdx.x;
    const int lane = t & 31;
    const int warp = t >> 5;

    #pragma unroll
    for (int i = t; i < 256; i += TPB) sWin[i] = Win[i];
    __syncthreads();                           // weights visible; only block barrier pre-finalize

    const int half = lane >> 4;                // 0: chunks 0-7, 1: chunks 8-15
    const int r16  = lane & 15;                // row within sub-tile
    const int rx   = r16 & 7;
    const int cgrp = lane & 15;

    // stage-out weights in registers (constant per lane)
    const float4 q0 = Wout4[4 * cgrp + 0];
    const float4 q1 = Wout4[4 * cgrp + 1];
    const float4 q2 = Wout4[4 * cgrp + 2];
    const float4 q3 = Wout4[4 * cgrp + 3];

    const float4* w0 = reinterpret_cast<const float4*>(sWin);
    const float4* w1 = reinterpret_cast<const float4*>(sWin + 64);
    const float4* w2 = reinterpret_cast<const float4*>(sWin + 128);
    const float4* w3 = reinterpret_cast<const float4*>(sWin + 192);

    const unsigned int warpBase =
        ((unsigned int)blockIdx.x * 4 + warp) * (NT * TROWS);
    const float4* gin  = reinterpret_cast<const float4*>(ze) + (size_t)warpBase * 16;
    float4*       gout = reinterpret_cast<float4*>(zq)       + (size_t)warpBase * 16;

    prefetch_tile(buf[warp][0], gin);          // tile 0

    #pragma unroll 1
    for (int s = 0; s < NT; ++s) {
        if (s + 1 < NT) {
            prefetch_tile(buf[warp][(s + 1) & 1], gin + (s + 1) * (TROWS * 16));
            asm volatile("cp.async.wait_group 1;\n" ::: "memory"); // tile s ready
        } else {
            asm volatile("cp.async.wait_group 0;\n" ::: "memory");
        }
        __syncwarp();   // tile s visible; prior stage-out reads of sC complete

        // ---- compute: lane pair handles row r16 of sub-tile s ----
        {
            const float4* tb = buf[warp][s & 1];
            float a0 = 0.f, a1 = 0.f, a2 = 0.f, a3 = 0.f;
            #pragma unroll
            for (int i = 0; i < 8; i++) {
                int k = i + half * 8;                       // global chunk
                float4 v  = tb[(r16 << 4) | (k ^ rx)];
                float4 x0 = w0[k], x1 = w1[k], x2 = w2[k], x3 = w3[k];
                a0 = fmaf(v.x, x0.x, fmaf(v.y, x0.y, fmaf(v.z, x0.z, fmaf(v.w, x0.w, a0))));
                a1 = fmaf(v.x, x1.x, fmaf(v.y, x1.y, fmaf(v.z, x1.z, fmaf(v.w, x1.w, a1))));
                a2 = fmaf(v.x, x2.x, fmaf(v.y, x2.y, fmaf(v.z, x2.z, fmaf(v.w, x2.w, a2))));
                a3 = fmaf(v.x, x3.x, fmaf(v.y, x3.y, fmaf(v.z, x3.z, fmaf(v.w, x3.w, a3))));
            }
            // combine the two half-rows (4 shuffles; both lanes get full sums)
            a0 += __shfl_xor_sync(0xFFFFFFFFu, a0, 16);
            a1 += __shfl_xor_sync(0xFFFFFFFFu, a1, 16);
            a2 += __shfl_xor_sync(0xFFFFFFFFu, a2, 16);
            a3 += __shfl_xor_sync(0xFFFFFFFFu, a3, 16);

            // FSQ quantize: levels (8,8,8,2), strides (1,8,64,512)
            const float acc[4] = {a0, a1, a2, a3};
            const float Lm1[4] = {7.f, 7.f, 7.f, 1.f};
            const int   str[4] = {1, 8, 64, 512};
            float c[4];
            int index = 0;
            #pragma unroll
            for (int j = 0; j < 4; j++) {
                float u = (tanhf(acc[j]) + 1.0f) * 0.5f;
                float sc = u * Lm1[j];
                float r = rintf(sc);                  // round-half-even == jnp.round
                r = fminf(fmaxf(r, 0.0f), Lm1[j]);
                index += (int)r * str[j];
                c[j] = r - Lm1[j] * 0.5f;
            }

            if (half == 0) {
                __stcs(&idx_out[warpBase + s * TROWS + r16], (float)index);
                atomicAdd(&g_hist[index << HPAD], 1);
                sC[warp][r16] = make_float4(c[0], c[1], c[2], c[3]);
            }
        }
        __syncwarp();   // sC complete before stage-out reads

        // ---- stage out: regenerate outputs, contiguous 512B per store ----
        {
            float4* go = gout + s * (TROWS * 16);
            #pragma unroll
            for (int i = 0; i < 8; i++) {
                int f = lane + i * 32;
                int r = f >> 4;
                float4 cr = sC[warp][r];       // broadcast LDS.128 (2 rows/warp)
                float4 o;
                o.x = fmaf(cr.x, q0.x, fmaf(cr.y, q0.y, fmaf(cr.z, q0.z, cr.w * q0.w)));
                o.y = fmaf(cr.x, q1.x, fmaf(cr.y, q1.y, fmaf(cr.z, q1.z, cr.w * q1.w)));
                o.z = fmaf(cr.x, q2.x, fmaf(cr.y, q2.y, fmaf(cr.z, q2.z, cr.w * q2.w)));
                o.w = fmaf(cr.x, q3.x, fmaf(cr.y, q3.y, fmaf(cr.z, q3.z, cr.w * q3.w)));
                __stcs(&go[f], o);
            }
        }
    }

    // ---- last-block finalize (fused; no second launch) ----
    __threadfence();       // make this thread's hist REDs globally visible
    __syncthreads();       // all warps of this block done + fenced
    if (t == 0) {
        unsigned int v = atomicAdd(&g_done, 1u);
        isLast = (v == gridDim.x - 1);
    }
    __syncthreads();
    if (!isLast) return;

    __threadfence();   // acquire: all blocks' hist atomics visible
    float term = 0.f, nz = 0.f;
    #pragma unroll
    for (int i = t; i < NUM_CODES; i += TPB) {
        int cnt = g_hist[i << HPAD];
        g_hist[i << HPAD] = 0;                        // reset for next replay
        float p = (float)cnt * invB;
        term += p * logf(p + 1e-10f);
        nz   += (cnt > 0) ? 1.0f : 0.0f;
    }
    #pragma unroll
    for (int o = 16; o > 0; o >>= 1) {
        term += __shfl_down_sync(0xFFFFFFFFu, term, o);
        nz   += __shfl_down_sync(0xFFFFFFFFu, nz, o);
    }
    if ((t & 31) == 0) { red[t >> 5] = term; red[4 + (t >> 5)] = nz; }
    __syncthreads();
    if (t == 0) {
        float s = red[0] + red[1] + red[2] + red[3];
        float n = red[4] + red[5] + red[6] + red[7];
        scal[0] = 0.0f;                  // commitment_loss
        scal[1] = 0.0f;                  // codebook_loss
        scal[2] = expf(-s);              // perplexity
        scal[3] = n * (1.0f / 1024.0f);  // utilization
        g_done = 0;                      // reset for next replay
    }
}

// ---------------------------------------------------------------------------
extern "C" void kernel_launch(void* const* d_in, const int* in_sizes, int n_in,
                              void* d_out, int out_size) {
    const float* ze   = (const float*)d_in[0];  // (B, 64)
    const float* Win  = (const float*)d_in[1];  // (4, 64)
    const float* Wout = (const float*)d_in[2];  // (64, 4)

    const int B = in_sizes[0] / 64;
    float* out  = (float*)d_out;
    float* zq   = out;                       // B*64
    float* idxf = out + (size_t)B * 64;      // B
    float* scal = idxf + B;                  // 4 scalars

    const int grid = B / (4 * NT * TROWS);   // 524288 / 512 = 1024

    fsq_main<<<grid, TPB>>>(ze, Win, (const float4*)Wout,
                            zq, idxf, scal, 1.0f / (float)B);
}

// round 13
// speedup vs baseline: 1.2881x; 1.2881x over previous
#include <cuda_runtime.h>

#define NUM_CODES 1024
#define TPB 128              // threads per block == rows per tile
#define HPAD 5               // each hist bin on its own 128B line
#define TILE_BYTES 32768     // 128 rows x 256B, contiguous in global

__device__ int g_hist[NUM_CODES << HPAD];   // zero at load
__device__ unsigned int g_done;             // zero at load

// ---------------------------------------------------------------------------
// TMA-bulk streaming FSQ. One cp.async.bulk (32KB) in, compute, one
// cp.async.bulk (32KB) out. Global streams ride the TMA engine; LSU only
// carries conflict-free LDS/STS + one idx STG.32 + one hist RED per row.
// ---------------------------------------------------------------------------
__global__ __launch_bounds__(TPB, 6) void fsq_main(
    const float* __restrict__ ze,    // (B, 64)
    const float* __restrict__ Win,   // (4, 64) row-major
    const float4* __restrict__ Wout4,// (64) float4 rows
    float* __restrict__ zq,          // (B, 64)
    float* __restrict__ idx_out,     // (B,)
    float* __restrict__ scal,        // 4 scalars
    float invB)
{
    __shared__ float4 tile[TPB * 16];            // 32KB linear tile (in, then out)
    __shared__ float  sWin[256];                 // 4 x 64
    __shared__ float4 sC[TPB];                   // centered codes per row
    __shared__ __align__(8) unsigned long long mbar;
    __shared__ bool   isLast;
    __shared__ float  red[8];

    const int t = threadIdx.x;
    #pragma unroll
    for (int i = t; i < 256; i += TPB) sWin[i] = Win[i];

    const unsigned int tile_u32 = (unsigned int)__cvta_generic_to_shared(tile);
    const unsigned int mbar_u32 = (unsigned int)__cvta_generic_to_shared(&mbar);

    if (t == 0) {
        asm volatile("mbarrier.init.shared.b64 [%0], %1;"
                     :: "r"(mbar_u32), "r"(1u) : "memory");
    }
    __syncthreads();   // mbar init + sWin visible

    const unsigned int rowBase = (unsigned int)blockIdx.x * TPB;
    const float4* gin  = reinterpret_cast<const float4*>(ze) + (size_t)rowBase * 16;
    float4*       gout = reinterpret_cast<float4*>(zq)       + (size_t)rowBase * 16;

    // ---- stage in: ONE 32KB bulk copy, mbarrier-completed ----
    if (t == 0) {
        asm volatile("mbarrier.arrive.expect_tx.shared.b64 _, [%0], %1;"
                     :: "r"(mbar_u32), "r"((unsigned int)TILE_BYTES) : "memory");
        asm volatile("cp.async.bulk.shared::cta.global.mbarrier::complete_tx::bytes "
                     "[%0], [%1], %2, [%3];"
                     :: "r"(tile_u32), "l"(gin), "r"((unsigned int)TILE_BYTES),
                        "r"(mbar_u32) : "memory");
    }
    // wait (parity 0; barrier used once per block)
    {
        unsigned int done;
        asm volatile(
            "{\n\t.reg .pred p;\n\t"
            "mbarrier.try_wait.parity.acquire.cta.shared::cta.b64 p, [%1], 0;\n\t"
            "selp.b32 %0, 1, 0, p;\n\t}"
            : "=r"(done) : "r"(mbar_u32) : "memory");
        while (!done) {
            asm volatile(
                "{\n\t.reg .pred p;\n\t"
                "mbarrier.try_wait.parity.acquire.cta.shared::cta.b64 p, [%1], 0, 0x989680;\n\t"
                "selp.b32 %0, 1, 0, p;\n\t}"
                : "=r"(done) : "r"(mbar_u32) : "memory");
        }
    }

    // ---- compute: thread t owns row t; rotated reads are conflict-free ----
    {
        const float4* w0 = reinterpret_cast<const float4*>(sWin);
        const float4* w1 = reinterpret_cast<const float4*>(sWin + 64);
        const float4* w2 = reinterpret_cast<const float4*>(sWin + 128);
        const float4* w3 = reinterpret_cast<const float4*>(sWin + 192);
        const int rbase = t << 4;

        float a0 = 0.f, a1 = 0.f, a2 = 0.f, a3 = 0.f;
        #pragma unroll
        for (int k = 0; k < 16; k++) {
            int m = (k + t) & 15;            // rotation: 16B-group (k+t)&7 distinct per 8 lanes
            float4 v  = tile[rbase | m];
            float4 x0 = w0[m], x1 = w1[m], x2 = w2[m], x3 = w3[m];
            a0 = fmaf(v.x, x0.x, fmaf(v.y, x0.y, fmaf(v.z, x0.z, fmaf(v.w, x0.w, a0))));
            a1 = fmaf(v.x, x1.x, fmaf(v.y, x1.y, fmaf(v.z, x1.z, fmaf(v.w, x1.w, a1))));
            a2 = fmaf(v.x, x2.x, fmaf(v.y, x2.y, fmaf(v.z, x2.z, fmaf(v.w, x2.w, a2))));
            a3 = fmaf(v.x, x3.x, fmaf(v.y, x3.y, fmaf(v.z, x3.z, fmaf(v.w, x3.w, a3))));
        }

        // FSQ quantize: levels (8,8,8,2), strides (1,8,64,512)
        const float acc[4] = {a0, a1, a2, a3};
        const float Lm1[4] = {7.f, 7.f, 7.f, 1.f};
        const int   str[4] = {1, 8, 64, 512};
        float c[4];
        int index = 0;
        #pragma unroll
        for (int j = 0; j < 4; j++) {
            float u = (tanhf(acc[j]) + 1.0f) * 0.5f;
            float s = u * Lm1[j];
            float r = rintf(s);                       // round-half-even == jnp.round
            r = fminf(fmaxf(r, 0.0f), Lm1[j]);
            index += (int)r * str[j];
            c[j] = r - Lm1[j] * 0.5f;
        }

        __stcs(&idx_out[rowBase + t], (float)index);  // coalesced STG.32
        atomicAdd(&g_hist[index << HPAD], 1);         // 1 bin per 128B line

        sC[t] = make_float4(c[0], c[1], c[2], c[3]);
    }
    __syncthreads();   // all reads of tile done; sC complete

    // ---- stage out: regenerate outputs into the SAME tile, linear STS.128 ----
    // f = t + 128*i: column group f&15 == t&15 (constant), consecutive slots.
    {
        const int cgrp = t & 15;
        const float4 q0 = Wout4[4 * cgrp + 0];
        const float4 q1 = Wout4[4 * cgrp + 1];
        const float4 q2 = Wout4[4 * cgrp + 2];
        const float4 q3 = Wout4[4 * cgrp + 3];

        #pragma unroll
        for (int i = 0; i < 16; i++) {
            int f = t + i * TPB;
            float4 cr = sC[f >> 4];            // broadcast LDS.128 (2 rows/warp)
            float4 o;
            o.x = fmaf(cr.x, q0.x, fmaf(cr.y, q0.y, fmaf(cr.z, q0.z, cr.w * q0.w)));
            o.y = fmaf(cr.x, q1.x, fmaf(cr.y, q1.y, fmaf(cr.z, q1.z, cr.w * q1.w)));
            o.z = fmaf(cr.x, q2.x, fmaf(cr.y, q2.y, fmaf(cr.z, q2.z, cr.w * q2.w)));
            o.w = fmaf(cr.x, q3.x, fmaf(cr.y, q3.y, fmaf(cr.z, q3.z, cr.w * q3.w)));
            tile[f] = o;                       // conflict-free STS.128
        }
    }
    __syncthreads();   // output tile complete

    // ---- ONE 32KB bulk store via TMA engine ----
    if (t == 0) {
        asm volatile("fence.proxy.async.shared::cta;" ::: "memory");
        asm volatile("cp.async.bulk.global.shared::cta.bulk_group [%0], [%1], %2;"
                     :: "l"(gout), "r"(tile_u32), "r"((unsigned int)TILE_BYTES)
                     : "memory");
        asm volatile("cp.async.bulk.commit_group;" ::: "memory");
        asm volatile("cp.async.bulk.wait_group 0;" ::: "memory");
    }

    // ---- last-block finalize (fused; no second launch) ----
    __threadfence();       // make this thread's hist REDs globally visible
    __syncthreads();       // all warps done + fenced (and t0's bulk store waited)
    if (t == 0) {
        unsigned int v = atomicAdd(&g_done, 1u);
        isLast = (v == gridDim.x - 1);
    }
    __syncthreads();
    if (!isLast) return;

    __threadfence();   // acquire: all blocks' hist atomics visible
    float term = 0.f, nz = 0.f;
    #pragma unroll
    for (int i = t; i < NUM_CODES; i += TPB) {
        int cnt = g_hist[i << HPAD];
        g_hist[i << HPAD] = 0;                        // reset for next replay
        float p = (float)cnt * invB;
        term += p * logf(p + 1e-10f);
        nz   += (cnt > 0) ? 1.0f : 0.0f;
    }
    #pragma unroll
    for (int o = 16; o > 0; o >>= 1) {
        term += __shfl_down_sync(0xFFFFFFFFu, term, o);
        nz   += __shfl_down_sync(0xFFFFFFFFu, nz, o);
    }
    if ((t & 31) == 0) { red[t >> 5] = term; red[4 + (t >> 5)] = nz; }
    __syncthreads();
    if (t == 0) {
        float s = red[0] + red[1] + red[2] + red[3];
        float n = red[4] + red[5] + red[6] + red[7];
        scal[0] = 0.0f;                  // commitment_loss
        scal[1] = 0.0f;                  // codebook_loss
        scal[2] = expf(-s);              // perplexity
        scal[3] = n * (1.0f / 1024.0f);  // utilization
        g_done = 0;                      // reset for next replay
    }
}

// ---------------------------------------------------------------------------
extern "C" void kernel_launch(void* const* d_in, const int* in_sizes, int n_in,
                              void* d_out, int out_size) {
    const float* ze   = (const float*)d_in[0];  // (B, 64)
    const float* Win  = (const float*)d_in[1];  // (4, 64)
    const float* Wout = (const float*)d_in[2];  // (64, 4)

    const int B = in_sizes[0] / 64;
    float* out  = (float*)d_out;
    float* zq   = out;                       // B*64
    float* idxf = out + (size_t)B * 64;      // B
    float* scal = idxf + B;                  // 4 scalars

    const int grid = B / TPB;                // 524288 / 128 = 4096

    fsq_main<<<grid, TPB>>>(ze, Win, (const float4*)Wout,
                            zq, idxf, scal, 1.0f / (float)B);
}